// round 5
// baseline (speedup 1.0000x reference)
#include <cuda_runtime.h>
#include <cuda_fp16.h>
#include <cstdint>

// ---------------------------------------------------------------------------
// Problem shape (fixed by dataset)
// ---------------------------------------------------------------------------
static constexpr int GM = 8192;          // batch
static constexpr int GN = 512;           // out_count
static constexpr int GIN = 512;          // in_count
static constexpr int NB = 8;             // num_basis
static constexpr int GK = GIN * NB;      // 4096 (reduction dim, (i,m) order)

// GEMM tiling
static constexpr int BM = 128, BN = 128, BK = 64;
static constexpr int STAGES = 3;
static constexpr int KT = GK / BK;       // 64 k-tiles
static constexpr int LDS = BK + 8;       // 72 halves row stride (144B = 9*16B, conflict-free)
static constexpr int STAGE_BYTES = BM * LDS * 2;        // 18432 per operand
static constexpr int SMEM_BYTES = 2 * STAGES * STAGE_BYTES;  // 110592

// Scratch (allowed: __device__ globals)
__device__ __half g_basis[(size_t)GM * GK];   // 64 MB, [b][i*8+m]
__device__ __half g_coefh[(size_t)GN * GK];   // 4 MB,  [j][i*8+m]

// ---------------------------------------------------------------------------
// Helpers
// ---------------------------------------------------------------------------
__device__ __forceinline__ uint32_t h2_as_u32(__half2 v) {
    union { __half2 h; uint32_t u; } cvt;
    cvt.h = v;
    return cvt.u;
}

__device__ __forceinline__ uint32_t smem_u32(const void* p) {
    uint32_t a;
    asm("{ .reg .u64 t; cvta.to.shared.u64 t, %1; cvt.u32.u64 %0, t; }"
        : "=r"(a) : "l"(p));
    return a;
}

__device__ __forceinline__ void cp16(uint32_t dst, const void* src) {
    asm volatile("cp.async.cg.shared.global [%0], [%1], 16;\n" :: "r"(dst), "l"(src));
}

__device__ __forceinline__ void ldmatrix_x4(uint32_t* r, uint32_t addr) {
    asm volatile("ldmatrix.sync.aligned.m8n8.x4.shared.b16 {%0,%1,%2,%3}, [%4];"
                 : "=r"(r[0]), "=r"(r[1]), "=r"(r[2]), "=r"(r[3]) : "r"(addr));
}

__device__ __forceinline__ void mma_16816(float* d, const uint32_t* a, const uint32_t* b) {
    asm volatile(
        "mma.sync.aligned.m16n8k16.row.col.f32.f16.f16.f32 "
        "{%0,%1,%2,%3}, {%4,%5,%6,%7}, {%8,%9}, {%0,%1,%2,%3};"
        : "+f"(d[0]), "+f"(d[1]), "+f"(d[2]), "+f"(d[3])
        : "r"(a[0]), "r"(a[1]), "r"(a[2]), "r"(a[3]), "r"(b[0]), "r"(b[1]));
}

// ---------------------------------------------------------------------------
// Pass 1: basis expansion  s = 0.5*tanh(slope*(x-center)) + 0.5 -> fp16 scratch
// Thread owns one input-channel i; per-i constants folded into registers
// (t = f*x + g, f = slope, g = -slope*center), loops over BROWS batch rows.
// tanh.approx.f32: single MUFU op (vs EX2+RCP pair) — halves MUFU pressure.
// ---------------------------------------------------------------------------
static constexpr int BROWS = 16;   // batch rows per thread

__global__ void __launch_bounds__(256) basis_kernel(const float* __restrict__ x,
                                                    const float* __restrict__ centers,
                                                    const float* __restrict__ slopes) {
    int gt = blockIdx.x * blockDim.x + threadIdx.x;
    int i = gt & (GIN - 1);
    int b0 = (gt >> 9) * BROWS;

    const float4* c4 = reinterpret_cast<const float4*>(centers + (size_t)i * NB);
    const float4* s4 = reinterpret_cast<const float4*>(slopes + (size_t)i * NB);
    float4 c0 = c4[0], c1 = c4[1];
    float4 s0 = s4[0], s1 = s4[1];
    float cc[8] = {c0.x, c0.y, c0.z, c0.w, c1.x, c1.y, c1.z, c1.w};
    float ss[8] = {s0.x, s0.y, s0.z, s0.w, s1.x, s1.y, s1.z, s1.w};

    float f[8], g[8];
#pragma unroll
    for (int m = 0; m < 8; m++) {
        f[m] = ss[m];
        g[m] = -ss[m] * cc[m];
    }

    const float* xp = x + i;
    uint4* op = reinterpret_cast<uint4*>(g_basis) + i;

#pragma unroll 4
    for (int bb = 0; bb < BROWS; bb++) {
        int b = b0 + bb;
        float xv = xp[(size_t)b * GIN];
        __half h[8];
#pragma unroll
        for (int m = 0; m < 8; m++) {
            float t = fmaf(f[m], xv, g[m]);     // slope*(x-c)
            float th;
            asm("tanh.approx.f32 %0, %1;" : "=f"(th) : "f"(t));
            float s = fmaf(0.5f, th, 0.5f);
            h[m] = __float2half_rn(s);
        }
        uint4 o;
        o.x = h2_as_u32(__halves2half2(h[0], h[1]));
        o.y = h2_as_u32(__halves2half2(h[2], h[3]));
        o.z = h2_as_u32(__halves2half2(h[4], h[5]));
        o.w = h2_as_u32(__halves2half2(h[6], h[7]));
        op[(size_t)b * GIN] = o;
    }
}

// ---------------------------------------------------------------------------
// Pass 1b: coeffs fp32 -> fp16 (same [j][i*8+m] layout)
// ---------------------------------------------------------------------------
__global__ void __launch_bounds__(256) coef_convert_kernel(const float* __restrict__ c) {
    int idx = blockIdx.x * blockDim.x + threadIdx.x;   // per 4 elements
    float4 v = reinterpret_cast<const float4*>(c)[idx];
    __half2 a = __floats2half2_rn(v.x, v.y);
    __half2 b = __floats2half2_rn(v.z, v.w);
    uint2 o;
    o.x = h2_as_u32(a);
    o.y = h2_as_u32(b);
    reinterpret_cast<uint2*>(g_coefh)[idx] = o;
}

// ---------------------------------------------------------------------------
// Pass 2: HMMA GEMM  out[M,N] = basis[M,K] * coefh[N,K]^T  (fp32 accum)
// BM=128 BN=128 BK=64, 3-stage cp.async pipeline, 8 warps (2 M x 4 N),
// warp tile 64x32, mma.sync m16n8k16, B loaded via ldmatrix.x4 pairs.
// Next-stage loads are issued BEFORE the MMA block for max DMA/compute overlap.
// ---------------------------------------------------------------------------
__global__ void __launch_bounds__(256, 2) gemm_kernel(float* __restrict__ out) {
    extern __shared__ __half sm[];
    const uint32_t sbase = smem_u32(sm);

    const int tid = threadIdx.x;
    const int wid = tid >> 5;
    const int lid = tid & 31;
    const int wm = wid & 1;        // warp M index (0..1)  -> 64-row slab
    const int wn = wid >> 1;       // warp N index (0..3)  -> 32-col slab
    const int m0 = blockIdx.y * BM;
    const int n0 = blockIdx.x * BN;

    const __half* Abase = g_basis + (size_t)m0 * GK;
    const __half* Bbase = g_coefh + (size_t)n0 * GK;

    const uint32_t sA0 = sbase;
    const uint32_t sB0 = sbase + STAGES * STAGE_BYTES;

    auto load_stage = [&](int kt) {
        int stg = kt % STAGES;
        uint32_t sa = sA0 + stg * STAGE_BYTES;
        uint32_t sb = sB0 + stg * STAGE_BYTES;
        int kofs = kt * BK;
#pragma unroll
        for (int j = 0; j < 4; j++) {
            int c = tid + j * 256;
            int row = c >> 3;
            int cu = c & 7;
            uint32_t so = (uint32_t)(row * LDS + cu * 8) * 2;
            cp16(sa + so, Abase + (size_t)row * GK + kofs + cu * 8);
            cp16(sb + so, Bbase + (size_t)row * GK + kofs + cu * 8);
        }
        asm volatile("cp.async.commit_group;\n" ::: "memory");
    };

#pragma unroll
    for (int kt = 0; kt < STAGES - 1; kt++) load_stage(kt);

    float d[4][4][4];
#pragma unroll
    for (int mi = 0; mi < 4; mi++)
#pragma unroll
        for (int ni = 0; ni < 4; ni++)
#pragma unroll
            for (int q = 0; q < 4; q++) d[mi][ni][q] = 0.0f;

    // ldmatrix lane addressing (halves)
    const int a_row = wm * 64 + (lid & 15);
    const int a_col = (lid >> 4) * 8;
    const int b_row = wn * 32 + (lid & 7) + (lid >> 4) * 8;
    const int b_col = ((lid >> 3) & 1) * 8;

    for (int kt = 0; kt < KT; kt++) {
        int stg = kt % STAGES;
        asm volatile("cp.async.wait_group 1;\n" ::: "memory");
        __syncthreads();

        // Issue next-stage loads FIRST so the DMA overlaps this tile's MMAs.
        int ktn = kt + STAGES - 1;
        if (ktn < KT) {
            load_stage(ktn);
        } else {
            asm volatile("cp.async.commit_group;\n" ::: "memory");
        }

        uint32_t sa = sA0 + stg * STAGE_BYTES;
        uint32_t sb = sB0 + stg * STAGE_BYTES;

#pragma unroll
        for (int ks = 0; ks < 4; ks++) {
            uint32_t a[4][4];
            uint32_t b[4][2];
#pragma unroll
            for (int mi = 0; mi < 4; mi++) {
                uint32_t addr = sa + (uint32_t)((a_row + mi * 16) * LDS + ks * 16 + a_col) * 2;
                ldmatrix_x4(a[mi], addr);
            }
#pragma unroll
            for (int p = 0; p < 2; p++) {
                uint32_t t[4];
                uint32_t addr = sb + (uint32_t)((b_row + p * 16) * LDS + ks * 16 + b_col) * 2;
                ldmatrix_x4(t, addr);
                b[2 * p][0] = t[0]; b[2 * p][1] = t[1];
                b[2 * p + 1][0] = t[2]; b[2 * p + 1][1] = t[3];
            }
#pragma unroll
            for (int mi = 0; mi < 4; mi++)
#pragma unroll
                for (int ni = 0; ni < 4; ni++)
                    mma_16816(d[mi][ni], a[mi], b[ni]);
        }
    }

    // Epilogue: direct fp32 stores.
    const int er = m0 + wm * 64 + (lid >> 2);
    const int ec = n0 + wn * 32 + (lid & 3) * 2;
#pragma unroll
    for (int mi = 0; mi < 4; mi++) {
#pragma unroll
        for (int ni = 0; ni < 4; ni++) {
            int r = er + mi * 16;
            int c = ec + ni * 8;
            float2 v0 = make_float2(d[mi][ni][0], d[mi][ni][1]);
            float2 v1 = make_float2(d[mi][ni][2], d[mi][ni][3]);
            *reinterpret_cast<float2*>(out + (size_t)r * GN + c) = v0;
            *reinterpret_cast<float2*>(out + (size_t)(r + 8) * GN + c) = v1;
        }
    }
}

// ---------------------------------------------------------------------------
// Launch
// ---------------------------------------------------------------------------
extern "C" void kernel_launch(void* const* d_in, const int* in_sizes, int n_in,
                              void* d_out, int out_size) {
    const float* x       = (const float*)d_in[0];   // (8192, 512)
    const float* coeffs  = (const float*)d_in[1];   // (512, 512, 8)
    const float* centers = (const float*)d_in[2];   // (512, 8)
    const float* slopes  = (const float*)d_in[3];   // (512, 8)
    float* out = (float*)d_out;                     // (8192, 512)

    // Pass 1: basis expansion (thread per i, BROWS batch rows each)
    basis_kernel<<<(GM / BROWS) * GIN / 256, 256>>>(x, centers, slopes);

    // Pass 1b: coeffs fp32 -> fp16
    coef_convert_kernel<<<(GN * GK / 4) / 256, 256>>>(coeffs);

    // Pass 2: HMMA GEMM
    cudaFuncSetAttribute(gemm_kernel, cudaFuncAttributeMaxDynamicSharedMemorySize,
                         SMEM_BYTES);
    dim3 grid(GN / BN, GM / BM);   // (4, 64)
    gemm_kernel<<<grid, 256, SMEM_BYTES>>>(out);
}

// round 6
// speedup vs baseline: 1.1002x; 1.1002x over previous
#include <cuda_runtime.h>
#include <cuda_fp16.h>
#include <cstdint>

// ---------------------------------------------------------------------------
// Problem shape (fixed by dataset)
// ---------------------------------------------------------------------------
static constexpr int GM = 8192;          // batch
static constexpr int GN = 512;           // out_count
static constexpr int GIN = 512;          // in_count
static constexpr int NB = 8;             // num_basis
static constexpr int GK = GIN * NB;      // 4096 (reduction dim, (i,m) order)

// GEMM tiling: BM=128, BN=256, BK=64; 8 warps in 2(M) x 4(N); warp tile 64x64
static constexpr int BM = 128, BN = 256, BK = 64;
static constexpr int STAGES = 3;
static constexpr int KT = GK / BK;       // 64 k-tiles
static constexpr int LDS = BK + 8;       // 72 halves row stride (144B, conflict-free)
static constexpr int A_STAGE_BYTES = BM * LDS * 2;   // 18432
static constexpr int B_STAGE_BYTES = BN * LDS * 2;   // 36864
static constexpr int SMEM_BYTES = STAGES * (A_STAGE_BYTES + B_STAGE_BYTES);  // 165888

// Scratch (allowed: __device__ globals)
__device__ __half g_basis[(size_t)GM * GK];   // 64 MB, [b][i*8+m]
__device__ __half g_coefh[(size_t)GN * GK];   // 4 MB,  [j][i*8+m]

// ---------------------------------------------------------------------------
// Helpers
// ---------------------------------------------------------------------------
__device__ __forceinline__ uint32_t h2_as_u32(__half2 v) {
    union { __half2 h; uint32_t u; } cvt;
    cvt.h = v;
    return cvt.u;
}

__device__ __forceinline__ uint32_t smem_u32(const void* p) {
    uint32_t a;
    asm("{ .reg .u64 t; cvta.to.shared.u64 t, %1; cvt.u32.u64 %0, t; }"
        : "=r"(a) : "l"(p));
    return a;
}

__device__ __forceinline__ void cp16(uint32_t dst, const void* src) {
    asm volatile("cp.async.cg.shared.global [%0], [%1], 16;\n" :: "r"(dst), "l"(src));
}

__device__ __forceinline__ void ldmatrix_x4(uint32_t* r, uint32_t addr) {
    asm volatile("ldmatrix.sync.aligned.m8n8.x4.shared.b16 {%0,%1,%2,%3}, [%4];"
                 : "=r"(r[0]), "=r"(r[1]), "=r"(r[2]), "=r"(r[3]) : "r"(addr));
}

__device__ __forceinline__ void mma_16816(float* d, const uint32_t* a, const uint32_t* b) {
    asm volatile(
        "mma.sync.aligned.m16n8k16.row.col.f32.f16.f16.f32 "
        "{%0,%1,%2,%3}, {%4,%5,%6,%7}, {%8,%9}, {%0,%1,%2,%3};"
        : "+f"(d[0]), "+f"(d[1]), "+f"(d[2]), "+f"(d[3])
        : "r"(a[0]), "r"(a[1]), "r"(a[2]), "r"(a[3]), "r"(b[0]), "r"(b[1]));
}

// ---------------------------------------------------------------------------
// Pass 1: basis expansion  s = 0.5*tanh(slope*(x-center)) + 0.5 -> fp16 scratch
// ---------------------------------------------------------------------------
static constexpr int BROWS = 16;   // batch rows per thread

__global__ void __launch_bounds__(256) basis_kernel(const float* __restrict__ x,
                                                    const float* __restrict__ centers,
                                                    const float* __restrict__ slopes) {
    int gt = blockIdx.x * blockDim.x + threadIdx.x;
    int i = gt & (GIN - 1);
    int b0 = (gt >> 9) * BROWS;

    const float4* c4 = reinterpret_cast<const float4*>(centers + (size_t)i * NB);
    const float4* s4 = reinterpret_cast<const float4*>(slopes + (size_t)i * NB);
    float4 c0 = c4[0], c1 = c4[1];
    float4 s0 = s4[0], s1 = s4[1];
    float cc[8] = {c0.x, c0.y, c0.z, c0.w, c1.x, c1.y, c1.z, c1.w};
    float ss[8] = {s0.x, s0.y, s0.z, s0.w, s1.x, s1.y, s1.z, s1.w};

    float f[8], g[8];
#pragma unroll
    for (int m = 0; m < 8; m++) {
        f[m] = ss[m];
        g[m] = -ss[m] * cc[m];
    }

    const float* xp = x + i;
    uint4* op = reinterpret_cast<uint4*>(g_basis) + i;

#pragma unroll 4
    for (int bb = 0; bb < BROWS; bb++) {
        int b = b0 + bb;
        float xv = xp[(size_t)b * GIN];
        __half h[8];
#pragma unroll
        for (int m = 0; m < 8; m++) {
            float t = fmaf(f[m], xv, g[m]);     // slope*(x-c)
            float th;
            asm("tanh.approx.f32 %0, %1;" : "=f"(th) : "f"(t));
            float s = fmaf(0.5f, th, 0.5f);
            h[m] = __float2half_rn(s);
        }
        uint4 o;
        o.x = h2_as_u32(__halves2half2(h[0], h[1]));
        o.y = h2_as_u32(__halves2half2(h[2], h[3]));
        o.z = h2_as_u32(__halves2half2(h[4], h[5]));
        o.w = h2_as_u32(__halves2half2(h[6], h[7]));
        op[(size_t)b * GIN] = o;
    }
}

// ---------------------------------------------------------------------------
// Pass 1b: coeffs fp32 -> fp16 (same [j][i*8+m] layout)
// ---------------------------------------------------------------------------
__global__ void __launch_bounds__(256) coef_convert_kernel(const float* __restrict__ c) {
    int idx = blockIdx.x * blockDim.x + threadIdx.x;   // per 4 elements
    float4 v = reinterpret_cast<const float4*>(c)[idx];
    __half2 a = __floats2half2_rn(v.x, v.y);
    __half2 b = __floats2half2_rn(v.z, v.w);
    uint2 o;
    o.x = h2_as_u32(a);
    o.y = h2_as_u32(b);
    reinterpret_cast<uint2*>(g_coefh)[idx] = o;
}

// ---------------------------------------------------------------------------
// Pass 2: HMMA GEMM  out[M,N] = basis[M,K] * coefh[N,K]^T  (fp32 accum)
// BM=128 BN=256 BK=64, 3-stage cp.async pipeline, 8 warps (2 M x 4 N),
// warp tile 64x64 (halves B-fragment smem redundancy vs 64x32).
// Loads issued AFTER the MMA block (empirically faster than before).
// ---------------------------------------------------------------------------
__global__ void __launch_bounds__(256, 1) gemm_kernel(float* __restrict__ out) {
    extern __shared__ __half sm[];
    const uint32_t sbase = smem_u32(sm);

    const int tid = threadIdx.x;
    const int wid = tid >> 5;
    const int lid = tid & 31;
    const int wm = wid & 1;        // warp M index (0..1)  -> 64-row slab
    const int wn = wid >> 1;       // warp N index (0..3)  -> 64-col slab
    const int m0 = blockIdx.y * BM;
    const int n0 = blockIdx.x * BN;

    const __half* Abase = g_basis + (size_t)m0 * GK;
    const __half* Bbase = g_coefh + (size_t)n0 * GK;

    const uint32_t sA0 = sbase;
    const uint32_t sB0 = sbase + STAGES * A_STAGE_BYTES;

    // cp.async per stage: A = 1024 chunks (4/thread), B = 2048 chunks (8/thread)
    auto load_stage = [&](int kt) {
        int stg = kt % STAGES;
        uint32_t sa = sA0 + stg * A_STAGE_BYTES;
        uint32_t sb = sB0 + stg * B_STAGE_BYTES;
        int kofs = kt * BK;
#pragma unroll
        for (int j = 0; j < 4; j++) {
            int c = tid + j * 256;
            int row = c >> 3;
            int cu = c & 7;
            uint32_t so = (uint32_t)(row * LDS + cu * 8) * 2;
            cp16(sa + so, Abase + (size_t)row * GK + kofs + cu * 8);
        }
#pragma unroll
        for (int j = 0; j < 8; j++) {
            int c = tid + j * 256;
            int row = c >> 3;
            int cu = c & 7;
            uint32_t so = (uint32_t)(row * LDS + cu * 8) * 2;
            cp16(sb + so, Bbase + (size_t)row * GK + kofs + cu * 8);
        }
        asm volatile("cp.async.commit_group;\n" ::: "memory");
    };

#pragma unroll
    for (int kt = 0; kt < STAGES - 1; kt++) load_stage(kt);

    float d[4][8][4];
#pragma unroll
    for (int mi = 0; mi < 4; mi++)
#pragma unroll
        for (int ni = 0; ni < 8; ni++)
#pragma unroll
            for (int q = 0; q < 4; q++) d[mi][ni][q] = 0.0f;

    // ldmatrix lane addressing (halves)
    const int a_row = wm * 64 + (lid & 15);
    const int a_col = (lid >> 4) * 8;
    const int b_row = wn * 64 + (lid & 7) + (lid >> 4) * 8;
    const int b_col = ((lid >> 3) & 1) * 8;

    for (int kt = 0; kt < KT; kt++) {
        int stg = kt % STAGES;
        asm volatile("cp.async.wait_group 1;\n" ::: "memory");
        __syncthreads();

        uint32_t sa = sA0 + stg * A_STAGE_BYTES;
        uint32_t sb = sB0 + stg * B_STAGE_BYTES;

#pragma unroll
        for (int ks = 0; ks < 4; ks++) {
            uint32_t a[4][4];
            uint32_t b[8][2];
#pragma unroll
            for (int mi = 0; mi < 4; mi++) {
                uint32_t addr = sa + (uint32_t)((a_row + mi * 16) * LDS + ks * 16 + a_col) * 2;
                ldmatrix_x4(a[mi], addr);
            }
#pragma unroll
            for (int p = 0; p < 4; p++) {
                uint32_t t[4];
                uint32_t addr = sb + (uint32_t)((b_row + p * 16) * LDS + ks * 16 + b_col) * 2;
                ldmatrix_x4(t, addr);
                b[2 * p][0] = t[0]; b[2 * p][1] = t[1];
                b[2 * p + 1][0] = t[2]; b[2 * p + 1][1] = t[3];
            }
#pragma unroll
            for (int mi = 0; mi < 4; mi++)
#pragma unroll
                for (int ni = 0; ni < 8; ni++)
                    mma_16816(d[mi][ni], a[mi], b[ni]);
        }

        int ktn = kt + STAGES - 1;
        if (ktn < KT) {
            load_stage(ktn);
        } else {
            asm volatile("cp.async.commit_group;\n" ::: "memory");
        }
    }

    // Epilogue: direct fp32 stores.
    const int er = m0 + wm * 64 + (lid >> 2);
    const int ec = n0 + wn * 64 + (lid & 3) * 2;
#pragma unroll
    for (int mi = 0; mi < 4; mi++) {
#pragma unroll
        for (int ni = 0; ni < 8; ni++) {
            int r = er + mi * 16;
            int c = ec + ni * 8;
            float2 v0 = make_float2(d[mi][ni][0], d[mi][ni][1]);
            float2 v1 = make_float2(d[mi][ni][2], d[mi][ni][3]);
            *reinterpret_cast<float2*>(out + (size_t)r * GN + c) = v0;
            *reinterpret_cast<float2*>(out + (size_t)(r + 8) * GN + c) = v1;
        }
    }
}

// ---------------------------------------------------------------------------
// Launch
// ---------------------------------------------------------------------------
extern "C" void kernel_launch(void* const* d_in, const int* in_sizes, int n_in,
                              void* d_out, int out_size) {
    const float* x       = (const float*)d_in[0];   // (8192, 512)
    const float* coeffs  = (const float*)d_in[1];   // (512, 512, 8)
    const float* centers = (const float*)d_in[2];   // (512, 8)
    const float* slopes  = (const float*)d_in[3];   // (512, 8)
    float* out = (float*)d_out;                     // (8192, 512)

    // Pass 1: basis expansion (thread per i, BROWS batch rows each)
    basis_kernel<<<(GM / BROWS) * GIN / 256, 256>>>(x, centers, slopes);

    // Pass 1b: coeffs fp32 -> fp16
    coef_convert_kernel<<<(GN * GK / 4) / 256, 256>>>(coeffs);

    // Pass 2: HMMA GEMM
    cudaFuncSetAttribute(gemm_kernel, cudaFuncAttributeMaxDynamicSharedMemorySize,
                         SMEM_BYTES);
    dim3 grid(GN / BN, GM / BM);   // (2, 64)
    gemm_kernel<<<grid, 256, SMEM_BYTES>>>(out);
}

// round 7
// speedup vs baseline: 1.1345x; 1.0311x over previous
#include <cuda_runtime.h>
#include <cuda_fp16.h>
#include <cstdint>

// ---------------------------------------------------------------------------
// Problem shape (fixed by dataset)
// ---------------------------------------------------------------------------
static constexpr int GM = 8192;          // batch
static constexpr int GN = 512;           // out_count
static constexpr int GIN = 512;          // in_count
static constexpr int NB = 8;             // num_basis
static constexpr int GK = GIN * NB;      // 4096 (reduction dim, (i,m) order)

// GEMM tiling: BM=128, BN=256, BK=64; 8 warps in 2(M) x 4(N); warp tile 64x64
static constexpr int BM = 128, BN = 256, BK = 64;
static constexpr int STAGES = 3;
static constexpr int KT = GK / BK;       // 64 k-tiles
static constexpr int LDS = BK + 8;       // 72 halves row stride (144B, conflict-free)
static constexpr int A_STAGE_BYTES = BM * LDS * 2;   // 18432
static constexpr int B_STAGE_BYTES = BN * LDS * 2;   // 36864
static constexpr int SMEM_BYTES = STAGES * (A_STAGE_BYTES + B_STAGE_BYTES);  // 165888

// Scratch (allowed: __device__ globals)
__device__ __half g_basis[(size_t)GM * GK];   // 64 MB, [b][i*8+m]
__device__ __half g_coefh[(size_t)GN * GK];   // 4 MB,  [j][i*8+m]

// ---------------------------------------------------------------------------
// Helpers
// ---------------------------------------------------------------------------
__device__ __forceinline__ uint32_t h2_as_u32(__half2 v) {
    union { __half2 h; uint32_t u; } cvt;
    cvt.h = v;
    return cvt.u;
}

__device__ __forceinline__ uint32_t smem_u32(const void* p) {
    uint32_t a;
    asm("{ .reg .u64 t; cvta.to.shared.u64 t, %1; cvt.u32.u64 %0, t; }"
        : "=r"(a) : "l"(p));
    return a;
}

__device__ __forceinline__ void cp16(uint32_t dst, const void* src) {
    asm volatile("cp.async.cg.shared.global [%0], [%1], 16;\n" :: "r"(dst), "l"(src));
}

__device__ __forceinline__ void ldmatrix_x4(uint32_t* r, uint32_t addr) {
    asm volatile("ldmatrix.sync.aligned.m8n8.x4.shared.b16 {%0,%1,%2,%3}, [%4];"
                 : "=r"(r[0]), "=r"(r[1]), "=r"(r[2]), "=r"(r[3]) : "r"(addr));
}

__device__ __forceinline__ void mma_16816(float* d, const uint32_t* a, const uint32_t* b) {
    asm volatile(
        "mma.sync.aligned.m16n8k16.row.col.f32.f16.f16.f32 "
        "{%0,%1,%2,%3}, {%4,%5,%6,%7}, {%8,%9}, {%0,%1,%2,%3};"
        : "+f"(d[0]), "+f"(d[1]), "+f"(d[2]), "+f"(d[3])
        : "r"(a[0]), "r"(a[1]), "r"(a[2]), "r"(a[3]), "r"(b[0]), "r"(b[1]));
}

// ---------------------------------------------------------------------------
// Pass 1: basis expansion  s = 0.5*tanh(slope*(x-center)) + 0.5 -> fp16 scratch
// x loads are batched first (MLP=BROWS) so memory latency fully overlaps
// the MUFU tanh chain.
// ---------------------------------------------------------------------------
static constexpr int BROWS = 16;   // batch rows per thread

__global__ void __launch_bounds__(256) basis_kernel(const float* __restrict__ x,
                                                    const float* __restrict__ centers,
                                                    const float* __restrict__ slopes) {
    int gt = blockIdx.x * blockDim.x + threadIdx.x;
    int i = gt & (GIN - 1);
    int b0 = (gt >> 9) * BROWS;

    const float4* c4 = reinterpret_cast<const float4*>(centers + (size_t)i * NB);
    const float4* s4 = reinterpret_cast<const float4*>(slopes + (size_t)i * NB);
    float4 c0 = c4[0], c1 = c4[1];
    float4 s0 = s4[0], s1 = s4[1];
    float cc[8] = {c0.x, c0.y, c0.z, c0.w, c1.x, c1.y, c1.z, c1.w};
    float ss[8] = {s0.x, s0.y, s0.z, s0.w, s1.x, s1.y, s1.z, s1.w};

    float f[8], g[8];
#pragma unroll
    for (int m = 0; m < 8; m++) {
        f[m] = ss[m];
        g[m] = -ss[m] * cc[m];
    }

    const float* xp = x + i;
    uint4* op = reinterpret_cast<uint4*>(g_basis) + i;

    float xv[BROWS];
#pragma unroll
    for (int bb = 0; bb < BROWS; bb++)
        xv[bb] = xp[(size_t)(b0 + bb) * GIN];

#pragma unroll
    for (int bb = 0; bb < BROWS; bb++) {
        __half h[8];
#pragma unroll
        for (int m = 0; m < 8; m++) {
            float t = fmaf(f[m], xv[bb], g[m]);   // slope*(x-c)
            float th;
            asm("tanh.approx.f32 %0, %1;" : "=f"(th) : "f"(t));
            float s = fmaf(0.5f, th, 0.5f);
            h[m] = __float2half_rn(s);
        }
        uint4 o;
        o.x = h2_as_u32(__halves2half2(h[0], h[1]));
        o.y = h2_as_u32(__halves2half2(h[2], h[3]));
        o.z = h2_as_u32(__halves2half2(h[4], h[5]));
        o.w = h2_as_u32(__halves2half2(h[6], h[7]));
        op[(size_t)(b0 + bb) * GIN] = o;
    }
}

// ---------------------------------------------------------------------------
// Pass 1b: coeffs fp32 -> fp16 (same [j][i*8+m] layout)
// ---------------------------------------------------------------------------
__global__ void __launch_bounds__(256) coef_convert_kernel(const float* __restrict__ c) {
    int idx = blockIdx.x * blockDim.x + threadIdx.x;   // per 4 elements
    float4 v = reinterpret_cast<const float4*>(c)[idx];
    __half2 a = __floats2half2_rn(v.x, v.y);
    __half2 b = __floats2half2_rn(v.z, v.w);
    uint2 o;
    o.x = h2_as_u32(a);
    o.y = h2_as_u32(b);
    reinterpret_cast<uint2*>(g_coefh)[idx] = o;
}

// ---------------------------------------------------------------------------
// Pass 2: HMMA GEMM  out[M,N] = basis[M,K] * coefh[N,K]^T  (fp32 accum)
// BM=128 BN=256 BK=64, 3-stage cp.async pipeline, 8 warps (2 M x 4 N),
// warp tile 64x64, register-level fragment double-buffering: ldmatrix for
// ks+1 issues while the 32 MMAs of ks execute.
// ---------------------------------------------------------------------------
__global__ void __launch_bounds__(256, 1) gemm_kernel(float* __restrict__ out) {
    extern __shared__ __half sm[];
    const uint32_t sbase = smem_u32(sm);

    const int tid = threadIdx.x;
    const int wid = tid >> 5;
    const int lid = tid & 31;
    const int wm = wid & 1;        // warp M index (0..1)  -> 64-row slab
    const int wn = wid >> 1;       // warp N index (0..3)  -> 64-col slab
    const int m0 = blockIdx.y * BM;
    const int n0 = blockIdx.x * BN;

    const __half* Abase = g_basis + (size_t)m0 * GK;
    const __half* Bbase = g_coefh + (size_t)n0 * GK;

    const uint32_t sA0 = sbase;
    const uint32_t sB0 = sbase + STAGES * A_STAGE_BYTES;

    auto load_stage = [&](int kt) {
        int stg = kt % STAGES;
        uint32_t sa = sA0 + stg * A_STAGE_BYTES;
        uint32_t sb = sB0 + stg * B_STAGE_BYTES;
        int kofs = kt * BK;
#pragma unroll
        for (int j = 0; j < 4; j++) {
            int c = tid + j * 256;
            int row = c >> 3;
            int cu = c & 7;
            uint32_t so = (uint32_t)(row * LDS + cu * 8) * 2;
            cp16(sa + so, Abase + (size_t)row * GK + kofs + cu * 8);
        }
#pragma unroll
        for (int j = 0; j < 8; j++) {
            int c = tid + j * 256;
            int row = c >> 3;
            int cu = c & 7;
            uint32_t so = (uint32_t)(row * LDS + cu * 8) * 2;
            cp16(sb + so, Bbase + (size_t)row * GK + kofs + cu * 8);
        }
        asm volatile("cp.async.commit_group;\n" ::: "memory");
    };

#pragma unroll
    for (int kt = 0; kt < STAGES - 1; kt++) load_stage(kt);

    float d[4][8][4];
#pragma unroll
    for (int mi = 0; mi < 4; mi++)
#pragma unroll
        for (int ni = 0; ni < 8; ni++)
#pragma unroll
            for (int q = 0; q < 4; q++) d[mi][ni][q] = 0.0f;

    // ldmatrix lane addressing (halves)
    const int a_row = wm * 64 + (lid & 15);
    const int a_col = (lid >> 4) * 8;
    const int b_row = wn * 64 + (lid & 7) + (lid >> 4) * 8;
    const int b_col = ((lid >> 3) & 1) * 8;

    uint32_t afr[2][4][4];
    uint32_t bfr[2][8][2];

    auto ld_frags = [&](uint32_t sa, uint32_t sb, int ks, int buf) {
#pragma unroll
        for (int mi = 0; mi < 4; mi++) {
            uint32_t addr = sa + (uint32_t)((a_row + mi * 16) * LDS + ks * 16 + a_col) * 2;
            ldmatrix_x4(afr[buf][mi], addr);
        }
#pragma unroll
        for (int p = 0; p < 4; p++) {
            uint32_t t[4];
            uint32_t addr = sb + (uint32_t)((b_row + p * 16) * LDS + ks * 16 + b_col) * 2;
            ldmatrix_x4(t, addr);
            bfr[buf][2 * p][0] = t[0]; bfr[buf][2 * p][1] = t[1];
            bfr[buf][2 * p + 1][0] = t[2]; bfr[buf][2 * p + 1][1] = t[3];
        }
    };

    for (int kt = 0; kt < KT; kt++) {
        int stg = kt % STAGES;
        asm volatile("cp.async.wait_group 1;\n" ::: "memory");
        __syncthreads();

        uint32_t sa = sA0 + stg * A_STAGE_BYTES;
        uint32_t sb = sB0 + stg * B_STAGE_BYTES;

        ld_frags(sa, sb, 0, 0);

#pragma unroll
        for (int ks = 0; ks < 4; ks++) {
            int cur = ks & 1;
            if (ks < 3) ld_frags(sa, sb, ks + 1, cur ^ 1);
#pragma unroll
            for (int mi = 0; mi < 4; mi++)
#pragma unroll
                for (int ni = 0; ni < 8; ni++)
                    mma_16816(d[mi][ni], afr[cur][mi], bfr[cur][ni]);
        }

        int ktn = kt + STAGES - 1;
        if (ktn < KT) {
            load_stage(ktn);
        } else {
            asm volatile("cp.async.commit_group;\n" ::: "memory");
        }
    }

    // Epilogue: direct fp32 stores.
    const int er = m0 + wm * 64 + (lid >> 2);
    const int ec = n0 + wn * 64 + (lid & 3) * 2;
#pragma unroll
    for (int mi = 0; mi < 4; mi++) {
#pragma unroll
        for (int ni = 0; ni < 8; ni++) {
            int r = er + mi * 16;
            int c = ec + ni * 8;
            float2 v0 = make_float2(d[mi][ni][0], d[mi][ni][1]);
            float2 v1 = make_float2(d[mi][ni][2], d[mi][ni][3]);
            *reinterpret_cast<float2*>(out + (size_t)r * GN + c) = v0;
            *reinterpret_cast<float2*>(out + (size_t)(r + 8) * GN + c) = v1;
        }
    }
}

// ---------------------------------------------------------------------------
// Launch
// ---------------------------------------------------------------------------
extern "C" void kernel_launch(void* const* d_in, const int* in_sizes, int n_in,
                              void* d_out, int out_size) {
    const float* x       = (const float*)d_in[0];   // (8192, 512)
    const float* coeffs  = (const float*)d_in[1];   // (512, 512, 8)
    const float* centers = (const float*)d_in[2];   // (512, 8)
    const float* slopes  = (const float*)d_in[3];   // (512, 8)
    float* out = (float*)d_out;                     // (8192, 512)

    // Pass 1: basis expansion (thread per i, BROWS batch rows each)
    basis_kernel<<<(GM / BROWS) * GIN / 256, 256>>>(x, centers, slopes);

    // Pass 1b: coeffs fp32 -> fp16
    coef_convert_kernel<<<(GN * GK / 4) / 256, 256>>>(coeffs);

    // Pass 2: HMMA GEMM
    cudaFuncSetAttribute(gemm_kernel, cudaFuncAttributeMaxDynamicSharedMemorySize,
                         SMEM_BYTES);
    dim3 grid(GN / BN, GM / BM);   // (2, 64)
    gemm_kernel<<<grid, 256, SMEM_BYTES>>>(out);
}